// round 1
// baseline (speedup 1.0000x reference)
#include <cuda_runtime.h>

// Problem constants
constexpr int B_ = 4;
constexpr int N_ = 2048;
constexpr int D_ = 1024;
constexpr int M_ = B_ * N_;   // 8192 rows for the projection GEMM

// Tiling
constexpr int BM = 128, BN = 128, BK = 16;
constexpr int TM = 8, TN = 8;

// Scratch (device globals — no allocation allowed)
__device__ float g_Q[B_ * N_ * D_];
__device__ float g_K[B_ * N_ * D_];
__device__ float g_V[B_ * N_ * D_];
__device__ float g_S[(size_t)B_ * N_ * N_];

// ---------------------------------------------------------------------------
// 1) QKV projection: C[8192,1024] = x[8192,1024] @ W[1024,1024]
//    blockIdx.z selects (Wq->g_Q, Wk->g_K, Wv->g_V)
// ---------------------------------------------------------------------------
__global__ __launch_bounds__(256) void proj_kernel(
    const float* __restrict__ x,
    const float* __restrict__ Wq,
    const float* __restrict__ Wk,
    const float* __restrict__ Wv) {
  const float* Bmat = (blockIdx.z == 0) ? Wq : (blockIdx.z == 1) ? Wk : Wv;
  float* C = (blockIdx.z == 0) ? g_Q : (blockIdx.z == 1) ? g_K : g_V;

  __shared__ float As[BK][BM];
  __shared__ float Bs[BK][BN];

  const int tid = threadIdx.x;
  const int ty = tid >> 4, tx = tid & 15;
  const int row0 = blockIdx.y * BM;
  const int col0 = blockIdx.x * BN;

  float acc[TM][TN] = {};

  for (int k0 = 0; k0 < D_; k0 += BK) {
    // A tile: BM x BK, transposed into As[k][m]
#pragma unroll
    for (int i = 0; i < 2; ++i) {
      int lin = tid + i * 256;            // 0..511
      int r = lin >> 2, c4 = lin & 3;     // r: 0..127, c4: 0..3
      float4 v = *(const float4*)(x + (size_t)(row0 + r) * D_ + k0 + c4 * 4);
      As[c4 * 4 + 0][r] = v.x;
      As[c4 * 4 + 1][r] = v.y;
      As[c4 * 4 + 2][r] = v.z;
      As[c4 * 4 + 3][r] = v.w;
    }
    // B tile: BK x BN, direct
#pragma unroll
    for (int i = 0; i < 2; ++i) {
      int lin = tid + i * 256;
      int r = lin >> 5, c4 = lin & 31;    // r: 0..15, c4: 0..31
      *(float4*)&Bs[r][c4 * 4] =
          *(const float4*)(Bmat + (size_t)(k0 + r) * D_ + col0 + c4 * 4);
    }
    __syncthreads();

#pragma unroll
    for (int kk = 0; kk < BK; ++kk) {
      float a[TM], b[TN];
      *(float4*)&a[0] = *(const float4*)&As[kk][ty * TM];
      *(float4*)&a[4] = *(const float4*)&As[kk][ty * TM + 4];
      *(float4*)&b[0] = *(const float4*)&Bs[kk][tx * TN];
      *(float4*)&b[4] = *(const float4*)&Bs[kk][tx * TN + 4];
#pragma unroll
      for (int i = 0; i < TM; ++i)
#pragma unroll
        for (int j = 0; j < TN; ++j)
          acc[i][j] = fmaf(a[i], b[j], acc[i][j]);
    }
    __syncthreads();
  }

#pragma unroll
  for (int i = 0; i < TM; ++i) {
    float* cp = C + (size_t)(row0 + ty * TM + i) * D_ + col0 + tx * TN;
    *(float4*)cp = make_float4(acc[i][0], acc[i][1], acc[i][2], acc[i][3]);
    *(float4*)(cp + 4) = make_float4(acc[i][4], acc[i][5], acc[i][6], acc[i][7]);
  }
}

// ---------------------------------------------------------------------------
// 2) Scores: S[b,q,k] = scale * dot(Q[b,q,:], K[b,k,:]); skip fully-masked
//    tiles (kb > qb). Masked entries inside a tile are left as-is; softmax
//    only ever reads k <= q.
// ---------------------------------------------------------------------------
__global__ __launch_bounds__(256) void scores_kernel() {
  const int kb = blockIdx.x, qb = blockIdx.y, b = blockIdx.z;
  if (kb > qb) return;  // tile entirely above the diagonal

  const float* Q = g_Q + (size_t)b * N_ * D_;
  const float* Kp = g_K + (size_t)b * N_ * D_;
  float* S = g_S + (size_t)b * N_ * N_;

  __shared__ float As[BK][BM];
  __shared__ float Bs[BK][BN];

  const int tid = threadIdx.x;
  const int ty = tid >> 4, tx = tid & 15;
  const int row0 = qb * BM;
  const int col0 = kb * BN;

  float acc[TM][TN] = {};

  for (int k0 = 0; k0 < D_; k0 += BK) {
#pragma unroll
    for (int i = 0; i < 2; ++i) {
      int lin = tid + i * 256;
      int r = lin >> 2, c4 = lin & 3;
      float4 v = *(const float4*)(Q + (size_t)(row0 + r) * D_ + k0 + c4 * 4);
      As[c4 * 4 + 0][r] = v.x;
      As[c4 * 4 + 1][r] = v.y;
      As[c4 * 4 + 2][r] = v.z;
      As[c4 * 4 + 3][r] = v.w;
      float4 w = *(const float4*)(Kp + (size_t)(col0 + r) * D_ + k0 + c4 * 4);
      Bs[c4 * 4 + 0][r] = w.x;
      Bs[c4 * 4 + 1][r] = w.y;
      Bs[c4 * 4 + 2][r] = w.z;
      Bs[c4 * 4 + 3][r] = w.w;
    }
    __syncthreads();

#pragma unroll
    for (int kk = 0; kk < BK; ++kk) {
      float a[TM], bb[TN];
      *(float4*)&a[0] = *(const float4*)&As[kk][ty * TM];
      *(float4*)&a[4] = *(const float4*)&As[kk][ty * TM + 4];
      *(float4*)&bb[0] = *(const float4*)&Bs[kk][tx * TN];
      *(float4*)&bb[4] = *(const float4*)&Bs[kk][tx * TN + 4];
#pragma unroll
      for (int i = 0; i < TM; ++i)
#pragma unroll
        for (int j = 0; j < TN; ++j)
          acc[i][j] = fmaf(a[i], bb[j], acc[i][j]);
    }
    __syncthreads();
  }

  const float scale = 0.03125f;  // 1/sqrt(1024)
#pragma unroll
  for (int i = 0; i < TM; ++i) {
    float* sp = S + (size_t)(row0 + ty * TM + i) * N_ + col0 + tx * TN;
    *(float4*)sp = make_float4(acc[i][0] * scale, acc[i][1] * scale,
                               acc[i][2] * scale, acc[i][3] * scale);
    *(float4*)(sp + 4) = make_float4(acc[i][4] * scale, acc[i][5] * scale,
                                     acc[i][6] * scale, acc[i][7] * scale);
  }
}

// ---------------------------------------------------------------------------
// 3) Causal softmax per row. Reads only k <= q; writes the full row with
//    zeros beyond the diagonal so P*V can run dense-bounded.
// ---------------------------------------------------------------------------
__global__ __launch_bounds__(256) void softmax_kernel() {
  const int q = blockIdx.x, b = blockIdx.y;
  float* row = g_S + ((size_t)b * N_ + q) * N_;
  const int L = q + 1;
  const int tid = threadIdx.x;

  __shared__ float red[256];

  // max
  float m = -1e30f;
  for (int k = tid; k < L; k += 256) m = fmaxf(m, row[k]);
  red[tid] = m;
  __syncthreads();
  for (int s = 128; s > 0; s >>= 1) {
    if (tid < s) red[tid] = fmaxf(red[tid], red[tid + s]);
    __syncthreads();
  }
  m = red[0];
  __syncthreads();

  // sum of exp
  float sum = 0.f;
  for (int k = tid; k < L; k += 256) sum += expf(row[k] - m);
  red[tid] = sum;
  __syncthreads();
  for (int s = 128; s > 0; s >>= 1) {
    if (tid < s) red[tid] += red[tid + s];
    __syncthreads();
  }
  sum = red[0];
  __syncthreads();

  const float inv = 1.f / sum;
  for (int k = tid; k < N_; k += 256) {
    float p = (k < L) ? expf(row[k] - m) * inv : 0.f;
    row[k] = p;
  }
}

// ---------------------------------------------------------------------------
// 4) O = P @ V, K-loop bounded by the causal structure (keys beyond
//    qTileEnd are zero in P).
// ---------------------------------------------------------------------------
__global__ __launch_bounds__(256) void pv_kernel(float* __restrict__ out) {
  const int b = blockIdx.z;
  const float* P = g_S + (size_t)b * N_ * N_;
  const float* V = g_V + (size_t)b * N_ * D_;
  float* C = out + (size_t)b * N_ * D_;

  __shared__ float As[BK][BM];
  __shared__ float Bs[BK][BN];

  const int tid = threadIdx.x;
  const int ty = tid >> 4, tx = tid & 15;
  const int row0 = blockIdx.y * BM;
  const int col0 = blockIdx.x * BN;
  const int kEnd = row0 + BM;  // causal bound: max key used by this tile

  float acc[TM][TN] = {};

  for (int k0 = 0; k0 < kEnd; k0 += BK) {
#pragma unroll
    for (int i = 0; i < 2; ++i) {
      int lin = tid + i * 256;
      int r = lin >> 2, c4 = lin & 3;
      float4 v = *(const float4*)(P + (size_t)(row0 + r) * N_ + k0 + c4 * 4);
      As[c4 * 4 + 0][r] = v.x;
      As[c4 * 4 + 1][r] = v.y;
      As[c4 * 4 + 2][r] = v.z;
      As[c4 * 4 + 3][r] = v.w;
    }
#pragma unroll
    for (int i = 0; i < 2; ++i) {
      int lin = tid + i * 256;
      int r = lin >> 5, c4 = lin & 31;
      *(float4*)&Bs[r][c4 * 4] =
          *(const float4*)(V + (size_t)(k0 + r) * D_ + col0 + c4 * 4);
    }
    __syncthreads();

#pragma unroll
    for (int kk = 0; kk < BK; ++kk) {
      float a[TM], bb[TN];
      *(float4*)&a[0] = *(const float4*)&As[kk][ty * TM];
      *(float4*)&a[4] = *(const float4*)&As[kk][ty * TM + 4];
      *(float4*)&bb[0] = *(const float4*)&Bs[kk][tx * TN];
      *(float4*)&bb[4] = *(const float4*)&Bs[kk][tx * TN + 4];
#pragma unroll
      for (int i = 0; i < TM; ++i)
#pragma unroll
        for (int j = 0; j < TN; ++j)
          acc[i][j] = fmaf(a[i], bb[j], acc[i][j]);
    }
    __syncthreads();
  }

#pragma unroll
  for (int i = 0; i < TM; ++i) {
    float* cp = C + (size_t)(row0 + ty * TM + i) * D_ + col0 + tx * TN;
    *(float4*)cp = make_float4(acc[i][0], acc[i][1], acc[i][2], acc[i][3]);
    *(float4*)(cp + 4) = make_float4(acc[i][4], acc[i][5], acc[i][6], acc[i][7]);
  }
}

// ---------------------------------------------------------------------------
extern "C" void kernel_launch(void* const* d_in, const int* in_sizes, int n_in,
                              void* d_out, int out_size) {
  const float* x  = (const float*)d_in[0];
  const float* Wq = (const float*)d_in[1];
  const float* Wk = (const float*)d_in[2];
  const float* Wv = (const float*)d_in[3];
  float* out = (float*)d_out;

  // 1) QKV projections: M=8192, N=1024 -> grid (8, 64, 3)
  proj_kernel<<<dim3(D_ / BN, M_ / BM, 3), 256>>>(x, Wq, Wk, Wv);
  // 2) Scores: per batch 16x16 tiles (upper-triangular tiles early-exit)
  scores_kernel<<<dim3(N_ / BN, N_ / BM, B_), 256>>>();
  // 3) Causal softmax: one block per (q, b) row
  softmax_kernel<<<dim3(N_, B_), 256>>>();
  // 4) O = P @ V: per batch (8, 16) tiles
  pv_kernel<<<dim3(D_ / BN, N_ / BM, B_), 256>>>(out);
}

// round 3
// speedup vs baseline: 1.9610x; 1.9610x over previous
#include <cuda_runtime.h>
#include <cuda_bf16.h>
#include <cstdint>

// ---------------------------------------------------------------------------
// Problem constants
// ---------------------------------------------------------------------------
constexpr int B_ = 4;
constexpr int N_ = 2048;
constexpr int D_ = 1024;
constexpr int M_ = B_ * N_;  // 8192 tokens

// ---------------------------------------------------------------------------
// Scratch (device globals — allocation is forbidden)
// ---------------------------------------------------------------------------
__device__ __nv_bfloat16 g_xh[M_ * D_], g_xl[M_ * D_];
__device__ __nv_bfloat16 g_Wth[3][D_ * D_], g_Wtl[3][D_ * D_];  // W^T [e][d]
__device__ __nv_bfloat16 g_Qh[M_ * D_], g_Ql[M_ * D_];
__device__ __nv_bfloat16 g_Kh[M_ * D_], g_Kl[M_ * D_];
__device__ __nv_bfloat16 g_Vh[M_ * D_], g_Vl[M_ * D_];
__device__ __nv_bfloat16 g_Vth[B_][D_ * N_], g_Vtl[B_][D_ * N_];  // V^T [e][tok]
__device__ float g_S[(size_t)B_ * N_ * N_];
__device__ __nv_bfloat16 g_Ph[(size_t)B_ * N_ * N_], g_Pl[(size_t)B_ * N_ * N_];

// ---------------------------------------------------------------------------
// Helpers
// ---------------------------------------------------------------------------
__device__ __forceinline__ uint32_t smem_u32(const void* p) {
  uint32_t a;
  asm("{ .reg .u64 t; cvta.to.shared.u64 t, %1; cvt.u32.u64 %0, t; }"
      : "=r"(a) : "l"(p));
  return a;
}

__device__ __forceinline__ void cp_async16(uint32_t smem, const void* g) {
  asm volatile("cp.async.cg.shared.global [%0], [%1], 16;" ::"r"(smem), "l"(g)
               : "memory");
}
#define CP_COMMIT() asm volatile("cp.async.commit_group;" ::: "memory")

__device__ __forceinline__ uint32_t swz128(uint32_t off) {
  return off ^ ((off >> 3) & 0x70);
}

__device__ __forceinline__ void ldmatrix_x4(uint32_t& r0, uint32_t& r1,
                                            uint32_t& r2, uint32_t& r3,
                                            uint32_t addr) {
  asm volatile(
      "ldmatrix.sync.aligned.m8n8.x4.shared.b16 {%0,%1,%2,%3}, [%4];"
      : "=r"(r0), "=r"(r1), "=r"(r2), "=r"(r3)
      : "r"(addr));
}

__device__ __forceinline__ void mma_bf16(float* c, const uint32_t* a,
                                         uint32_t b0, uint32_t b1) {
  asm volatile(
      "mma.sync.aligned.m16n8k16.row.col.f32.bf16.bf16.f32 "
      "{%0,%1,%2,%3}, {%4,%5,%6,%7}, {%8,%9}, {%0,%1,%2,%3};"
      : "+f"(c[0]), "+f"(c[1]), "+f"(c[2]), "+f"(c[3])
      : "r"(a[0]), "r"(a[1]), "r"(a[2]), "r"(a[3]), "r"(b0), "r"(b1));
}

// ---------------------------------------------------------------------------
// Warp-tiled bf16 mma.sync GEMM, C[128x128] = A[128,K'] * B[128,K']^T.
// Both operands K-major. K' = hi/lo-tripled contraction:
// segments [A_hi*B_hi, A_lo*B_hi, A_hi*B_lo].
// mode 0: QKV proj (z=matrix)  mode 1: scores (z=batch)  mode 2: PV (z=batch)
// ---------------------------------------------------------------------------
constexpr int STAGE = 16384;  // 128 rows x 128B (BK = 64 bf16)
constexpr int SMEM_DYN = 1024 + 4 * STAGE;  // A[2] + B[2], 1KB align slack
constexpr float SCALE = 0.03125f;  // 1/sqrt(1024)

__global__ __launch_bounds__(256) void gemm_tc(int mode, float* out) {
  extern __shared__ char dsm[];

  const int bx = blockIdx.x, by = blockIdx.y, bz = blockIdx.z;
  const int row0 = by * 128, col0 = bx * 128;

  const __nv_bfloat16 *aH, *aL, *bH, *bL;
  size_t lda, ldb;
  int nk;
  if (mode == 0) {
    aH = g_xh; aL = g_xl;
    bH = g_Wth[bz]; bL = g_Wtl[bz];
    lda = D_; ldb = D_; nk = 16;
  } else if (mode == 1) {
    if (col0 > row0 + 127) return;  // tile fully above the diagonal
    size_t o = (size_t)bz * N_ * D_;
    aH = g_Qh + o; aL = g_Ql + o;
    bH = g_Kh + o; bL = g_Kl + o;
    lda = D_; ldb = D_; nk = 16;
  } else {
    size_t oa = (size_t)bz * N_ * N_;
    aH = g_Ph + oa; aL = g_Pl + oa;
    bH = g_Vth[bz]; bL = g_Vtl[bz];
    lda = N_; ldb = N_; nk = (row0 + 128) / 64;  // causal K bound
  }
  const int nchunks = 3 * nk;

  const int tid = threadIdx.x;
  const int wid = tid >> 5, lid = tid & 31;
  const int wm = wid & 3, wn = wid >> 2;  // 4 x 2 warp grid; warp tile 32x64

  const uint32_t smA = (smem_u32(dsm) + 1023) & ~1023u;
  const uint32_t smB = smA + 2 * STAGE;

  float acc[2][8][4];
#pragma unroll
  for (int i = 0; i < 2; ++i)
#pragma unroll
    for (int j = 0; j < 8; ++j)
#pragma unroll
      for (int k = 0; k < 4; ++k) acc[i][j][k] = 0.f;

  // ---- chunk loader: 256 threads, 8x cp.async 16B each ----
  auto load_chunk = [&](int c, int s) {
    const int seg = c / nk;
    const int k0 = (c - seg * nk) * 64;
    const __nv_bfloat16* a = (seg == 1) ? aL : aH;
    const __nv_bfloat16* b = (seg == 2) ? bL : bH;
    const int r = tid >> 1, h = tid & 1;
    const uint32_t o0 = (uint32_t)(r * 128 + h * 64);
    const char* ag = (const char*)(a + (size_t)(row0 + r) * lda + k0) + h * 64;
    const char* bg = (const char*)(b + (size_t)(col0 + r) * ldb + k0) + h * 64;
    const uint32_t sa = smA + s * STAGE, sb = smB + s * STAGE;
#pragma unroll
    for (int j = 0; j < 4; ++j) cp_async16(sa + swz128(o0 + j * 16), ag + j * 16);
#pragma unroll
    for (int j = 0; j < 4; ++j) cp_async16(sb + swz128(o0 + j * 16), bg + j * 16);
    CP_COMMIT();
  };

  load_chunk(0, 0);

  for (int c = 0; c < nchunks; ++c) {
    if (c + 1 < nchunks) {
      load_chunk(c + 1, (c + 1) & 1);
      asm volatile("cp.async.wait_group 1;" ::: "memory");
    } else {
      asm volatile("cp.async.wait_group 0;" ::: "memory");
    }
    __syncthreads();

    const uint32_t sa = smA + (c & 1) * STAGE;
    const uint32_t sb = smB + (c & 1) * STAGE;

#pragma unroll
    for (int kk = 0; kk < 4; ++kk) {  // 4 x k16 per 64-wide chunk
      uint32_t af[2][4];
#pragma unroll
      for (int mt = 0; mt < 2; ++mt) {
        const int m0 = wm * 32 + mt * 16;
        const int row = m0 + ((lid >> 3) & 1) * 8 + (lid & 7);
        const int kb = kk * 32 + ((lid >> 4) & 1) * 16;
        ldmatrix_x4(af[mt][0], af[mt][1], af[mt][2], af[mt][3],
                    sa + row * 128 + (kb ^ ((row & 7) << 4)));
      }
      uint32_t bfr[4][4];
#pragma unroll
      for (int np = 0; np < 4; ++np) {
        const int n0 = wn * 64 + np * 16;
        const int row = n0 + ((lid >> 4) & 1) * 8 + (lid & 7);
        const int kb = kk * 32 + ((lid >> 3) & 1) * 16;
        ldmatrix_x4(bfr[np][0], bfr[np][1], bfr[np][2], bfr[np][3],
                    sb + row * 128 + (kb ^ ((row & 7) << 4)));
      }
#pragma unroll
      for (int mt = 0; mt < 2; ++mt)
#pragma unroll
        for (int nt = 0; nt < 8; ++nt)
          mma_bf16(acc[mt][nt], af[mt], bfr[nt >> 1][(nt & 1) * 2],
                   bfr[nt >> 1][(nt & 1) * 2 + 1]);
    }
    __syncthreads();
  }

  // ---- epilogue: fragment (c0,c1)=(m, n..n+1), (c2,c3)=(m+8, n..n+1) ----
#pragma unroll
  for (int mt = 0; mt < 2; ++mt) {
#pragma unroll
    for (int nt = 0; nt < 8; ++nt) {
      const int m = row0 + wm * 32 + mt * 16 + (lid >> 2);
      const int n = col0 + wn * 64 + nt * 8 + 2 * (lid & 3);
      const float* cf = acc[mt][nt];
      if (mode == 0) {
        __nv_bfloat16* Ch = (bz == 0) ? g_Qh : (bz == 1) ? g_Kh : g_Vh;
        __nv_bfloat16* Cl = (bz == 0) ? g_Ql : (bz == 1) ? g_Kl : g_Vl;
#pragma unroll
        for (int hh = 0; hh < 2; ++hh) {
          const size_t o = (size_t)(m + hh * 8) * D_ + n;
          float v0 = cf[hh * 2], v1 = cf[hh * 2 + 1];
          __nv_bfloat16 h0 = __float2bfloat16(v0), h1 = __float2bfloat16(v1);
          *(__nv_bfloat162*)(Ch + o) = __nv_bfloat162(h0, h1);
          *(__nv_bfloat162*)(Cl + o) = __nv_bfloat162(
              __float2bfloat16(v0 - __bfloat162float(h0)),
              __float2bfloat16(v1 - __bfloat162float(h1)));
        }
      } else if (mode == 1) {
#pragma unroll
        for (int hh = 0; hh < 2; ++hh) {
          float* sp = g_S + ((size_t)bz * N_ + m + hh * 8) * N_ + n;
          sp[0] = cf[hh * 2] * SCALE;
          sp[1] = cf[hh * 2 + 1] * SCALE;
        }
      } else {
#pragma unroll
        for (int hh = 0; hh < 2; ++hh) {
          float* op = out + ((size_t)bz * N_ + m + hh * 8) * D_ + n;
          op[0] = cf[hh * 2];
          op[1] = cf[hh * 2 + 1];
        }
      }
    }
  }
}

// ---------------------------------------------------------------------------
// Conversions
// ---------------------------------------------------------------------------
__global__ __launch_bounds__(256) void conv_x_kernel(const float* __restrict__ x) {
  size_t i = ((size_t)blockIdx.x * 256 + threadIdx.x) * 4;
  float4 v = *(const float4*)(x + i);
  float vv[4] = {v.x, v.y, v.z, v.w};
#pragma unroll
  for (int j = 0; j < 4; ++j) {
    __nv_bfloat16 h = __float2bfloat16(vv[j]);
    g_xh[i + j] = h;
    g_xl[i + j] = __float2bfloat16(vv[j] - __bfloat162float(h));
  }
}

// transpose-convert W[d][e] -> Wt_hi/lo[e][d]
__global__ __launch_bounds__(256) void conv_w_kernel(const float* __restrict__ Wq,
                                                     const float* __restrict__ Wk,
                                                     const float* __restrict__ Wv) {
  const float* W = (blockIdx.z == 0) ? Wq : (blockIdx.z == 1) ? Wk : Wv;
  __nv_bfloat16* Th = g_Wth[blockIdx.z];
  __nv_bfloat16* Tl = g_Wtl[blockIdx.z];
  __shared__ float t[32][33];
  int tx = threadIdx.x & 31, ty = threadIdx.x >> 5;  // 32 x 8
  int d0 = blockIdx.y * 32, e0 = blockIdx.x * 32;
#pragma unroll
  for (int i = 0; i < 4; ++i)
    t[ty + i * 8][tx] = W[(size_t)(d0 + ty + i * 8) * D_ + e0 + tx];
  __syncthreads();
#pragma unroll
  for (int i = 0; i < 4; ++i) {
    float v = t[tx][ty + i * 8];
    __nv_bfloat16 h = __float2bfloat16(v);
    size_t o = (size_t)(e0 + ty + i * 8) * D_ + d0 + tx;
    Th[o] = h;
    Tl[o] = __float2bfloat16(v - __bfloat162float(h));
  }
}

// transpose V_hi/lo[b][tok][e] -> Vt_hi/lo[b][e][tok]
__global__ __launch_bounds__(256) void conv_vt_kernel() {
  __shared__ uint16_t th[32][33], tl[32][33];
  int tx = threadIdx.x & 31, ty = threadIdx.x >> 5;
  int tok0 = blockIdx.x * 32, e0 = blockIdx.y * 32, b = blockIdx.z;
  const uint16_t* Vh = (const uint16_t*)(g_Vh) + (size_t)b * N_ * D_;
  const uint16_t* Vl = (const uint16_t*)(g_Vl) + (size_t)b * N_ * D_;
#pragma unroll
  for (int i = 0; i < 4; ++i) {
    size_t o = (size_t)(tok0 + ty + i * 8) * D_ + e0 + tx;
    th[ty + i * 8][tx] = Vh[o];
    tl[ty + i * 8][tx] = Vl[o];
  }
  __syncthreads();
  uint16_t* Oh = (uint16_t*)g_Vth[b];
  uint16_t* Ol = (uint16_t*)g_Vtl[b];
#pragma unroll
  for (int i = 0; i < 4; ++i) {
    size_t o = (size_t)(e0 + ty + i * 8) * N_ + tok0 + tx;
    Oh[o] = th[tx][ty + i * 8];
    Ol[o] = tl[tx][ty + i * 8];
  }
}

// ---------------------------------------------------------------------------
// Causal softmax: reads S fp32 (k <= q only), writes P hi/lo bf16, zeros beyond
// ---------------------------------------------------------------------------
__global__ __launch_bounds__(256) void softmax_kernel() {
  const int q = blockIdx.x, b = blockIdx.y;
  const float* row = g_S + ((size_t)b * N_ + q) * N_;
  __nv_bfloat16* ph = g_Ph + ((size_t)b * N_ + q) * N_;
  __nv_bfloat16* pl = g_Pl + ((size_t)b * N_ + q) * N_;
  const int L = q + 1;
  const int tid = threadIdx.x;

  __shared__ float red[256];

  float m = -1e30f;
  for (int k = tid; k < L; k += 256) m = fmaxf(m, row[k]);
  red[tid] = m;
  __syncthreads();
  for (int s = 128; s > 0; s >>= 1) {
    if (tid < s) red[tid] = fmaxf(red[tid], red[tid + s]);
    __syncthreads();
  }
  m = red[0];
  __syncthreads();

  float sum = 0.f;
  for (int k = tid; k < L; k += 256) sum += expf(row[k] - m);
  red[tid] = sum;
  __syncthreads();
  for (int s = 128; s > 0; s >>= 1) {
    if (tid < s) red[tid] += red[tid + s];
    __syncthreads();
  }
  const float inv = 1.f / red[0];

  for (int k = tid; k < N_; k += 256) {
    if (k < L) {
      float p = expf(row[k] - m) * inv;
      __nv_bfloat16 h = __float2bfloat16(p);
      ph[k] = h;
      pl[k] = __float2bfloat16(p - __bfloat162float(h));
    } else {
      ph[k] = __float2bfloat16(0.f);
      pl[k] = __float2bfloat16(0.f);
    }
  }
}

// ---------------------------------------------------------------------------
extern "C" void kernel_launch(void* const* d_in, const int* in_sizes, int n_in,
                              void* d_out, int out_size) {
  const float* x  = (const float*)d_in[0];
  const float* Wq = (const float*)d_in[1];
  const float* Wk = (const float*)d_in[2];
  const float* Wv = (const float*)d_in[3];
  float* out = (float*)d_out;

  cudaFuncSetAttribute(gemm_tc, cudaFuncAttributeMaxDynamicSharedMemorySize,
                       SMEM_DYN);

  // 1) split inputs into bf16 hi/lo
  conv_x_kernel<<<(M_ * D_) / (256 * 4), 256>>>(x);
  conv_w_kernel<<<dim3(D_ / 32, D_ / 32, 3), 256>>>(Wq, Wk, Wv);
  // 2) QKV projections: C[8192,1024], 128x128 tiles
  gemm_tc<<<dim3(D_ / 128, M_ / 128, 3), 256, SMEM_DYN>>>(0, nullptr);
  // 3) transpose V for the PV GEMM
  conv_vt_kernel<<<dim3(N_ / 32, D_ / 32, B_), 256>>>();
  // 4) scores S = scale * Q K^T (tiles above the diagonal skipped)
  gemm_tc<<<dim3(N_ / 128, N_ / 128, B_), 256, SMEM_DYN>>>(1, nullptr);
  // 5) softmax -> P hi/lo
  softmax_kernel<<<dim3(N_, B_), 256>>>();
  // 6) O = P V (causally bounded K loop)
  gemm_tc<<<dim3(D_ / 128, N_ / 128, B_), 256, SMEM_DYN>>>(2, out);
}